// round 3
// baseline (speedup 1.0000x reference)
#include <cuda_runtime.h>

#define BATCH 4
#define NPTS  4096
#define KNB   20
#define EPSV  1e-5f
#define SLOPE 0.2f

#define PTS 16              // points per block (main kernel)
#define EDG (PTS * KNB)     // 320 edges per block
#define THR 256

#define QPW 8               // queries (=warps) per knn block
#define BUFCAP 384          // boundary-bin buffer capacity per warp
#define NLOC ((BUFCAP + 31) / 32)

// scratch (device globals; no allocations allowed)
__device__ float g_wp[384 * 64];          // reindexed + s1-folded w1: Wp[m*6+c][o]
__device__ float g_w0f[384];              // s0-folded w0
__device__ int   g_idx[BATCH * NPTS * KNB];

__device__ __forceinline__ float lrelu(float v) { return fmaxf(v, SLOPE * v); }

__device__ __forceinline__ float2 ffma2(float2 a, float2 b, float2 c) {
    float2 d;
    asm("fma.rn.f32x2 %0, %1, %2, %3;"
        : "=l"(reinterpret_cast<unsigned long long&>(d))
        : "l"(reinterpret_cast<unsigned long long&>(a)),
          "l"(reinterpret_cast<unsigned long long&>(b)),
          "l"(reinterpret_cast<unsigned long long&>(c)));
    return d;
}
__device__ __forceinline__ float2 fmul2(float2 a, float2 b) {
    float2 d;
    asm("mul.rn.f32x2 %0, %1, %2;"
        : "=l"(reinterpret_cast<unsigned long long&>(d))
        : "l"(reinterpret_cast<unsigned long long&>(a)),
          "l"(reinterpret_cast<unsigned long long&>(b)));
    return d;
}

// monotone float -> uint key (total order, incl. negatives)
__device__ __forceinline__ unsigned fkey(float d) {
    unsigned b = __float_as_uint(d);
    return b ^ ((unsigned)((int)b >> 31) | 0x80000000u);
}

// ---------------------------------------------------------------------------
// KNN via 2-pass histogram select (warp per query) + fused weight prep.
// Grid (NPTS/QPW, BATCH) = (512, 4), 256 threads (8 warps).
// Distance key: d = pp - 2*q.p (constant ||q||^2 shift of ||q-p||^2 preserves
// ordering; self point has minimal d, included — same as reference top_k).
// Pass 1: 256-bin histogram of key>>24; find boundary bin + m1 (count below).
// Pass 2: keys below bin -> g_idx directly (order irrelevant downstream);
//         keys in bin -> u64 buffer (key<<32|idx); select 20-m1 smallest by
//         repeated warp-min (exact, deterministic, ties by lower index).
// ---------------------------------------------------------------------------
__global__ void __launch_bounds__(256, 2) knn_prep_kernel(
    const float* __restrict__ x,
    const float* __restrict__ w0, const float* __restrict__ g0,
    const float* __restrict__ w1, const float* __restrict__ g1)
{
    extern __shared__ char dsm[];
    float4*             pts  = reinterpret_cast<float4*>(dsm);                    // 65536
    unsigned*           hist = reinterpret_cast<unsigned*>(dsm + 65536);          //  8192
    unsigned long long* buf  = reinterpret_cast<unsigned long long*>(dsm + 73728);// 24576
    unsigned*           cnto = reinterpret_cast<unsigned*>(dsm + 98304);          //    32
    unsigned*           cntb = cnto + 8;                                          //    32

    const int tid  = threadIdx.x;
    const int lane = tid & 31;
    const int w    = tid >> 5;
    const int b    = blockIdx.y;
    const int q    = blockIdx.x * QPW + w;
    const float* xb = x + b * 3 * NPTS;

    // ---- prep: distributed over the 2048 blocks ----
    {
        const int gt = (blockIdx.y * gridDim.x + blockIdx.x) * 256 + tid;
        const float inv = rsqrtf(1.f + EPSV);
        if (gt < 384) g_w0f[gt] = w0[gt] * g0[gt / 6] * inv;
        if (gt < 384 * 64) {
            int o  = gt & 63;
            int kc = gt >> 6;
            int m  = kc / 6;
            int c  = kc - m * 6;
            g_wp[gt] = g1[o] * inv * w1[(o * 6 + c) * 64 + m];
        }
    }

    // ---- stage batch points (x,y,z,||p||^2), zero hist/counters ----
    for (int i = tid; i < NPTS; i += 256) {
        float vx = xb[i], vy = xb[NPTS + i], vz = xb[2 * NPTS + i];
        pts[i] = make_float4(vx, vy, vz, fmaf(vx, vx, fmaf(vy, vy, vz * vz)));
    }
#pragma unroll
    for (int i = 0; i < 8; i++) hist[tid + i * 256] = 0;
    if (tid < 8) { cnto[tid] = 0; cntb[tid] = 0; }
    __syncthreads();

    const float4 qp = pts[q];
    const float qx = qp.x, qy = qp.y, qz = qp.z;
    unsigned* myh = hist + w * 256;

    // ---- pass 1: histogram on key>>24 ----
    for (int i = 0; i < NPTS / 32; i++) {
        float4 p = pts[(i << 5) + lane];
        float dot = fmaf(qx, p.x, fmaf(qy, p.y, qz * p.z));
        unsigned key = fkey(fmaf(-2.f, dot, p.w));
        unsigned bin = key >> 24;
        unsigned msk = __match_any_sync(0xffffffffu, bin);
        if (lane == (__ffs(msk) - 1)) atomicAdd(&myh[bin], __popc(msk));
    }
    __syncthreads();

    // ---- find boundary bin1 and m1 (exact count strictly below bin1) ----
    unsigned s = 0;
#pragma unroll
    for (int j = 0; j < 8; j++) s += myh[lane * 8 + j];
    unsigned incl = s;
#pragma unroll
    for (int d = 1; d < 32; d <<= 1) {
        unsigned t = __shfl_up_sync(0xffffffffu, incl, d);
        if (lane >= d) incl += t;
    }
    unsigned excl = incl - s;
    unsigned bal  = __ballot_sync(0xffffffffu, incl >= KNB);
    int L = __ffs(bal) - 1;
    int bin1l = 0; unsigned m1l = 0;
    if (lane == L) {
        unsigned cum = excl;
#pragma unroll
        for (int j = 0; j < 8; j++) {
            unsigned h = myh[lane * 8 + j];
            if (cum + h >= KNB) { bin1l = lane * 8 + j; m1l = cum; break; }
            cum += h;
        }
    }
    const unsigned bin1 = (unsigned)__shfl_sync(0xffffffffu, bin1l, L);
    const unsigned m1   = __shfl_sync(0xffffffffu, m1l, L);

    // ---- pass 2: emit below-bin directly; boundary bin -> buffer ----
    int* obase = g_idx + (b * NPTS + q) * KNB;
    unsigned long long* myb = buf + w * BUFCAP;
    for (int i = 0; i < NPTS / 32; i++) {
        int j = (i << 5) + lane;
        float4 p = pts[j];
        float dot = fmaf(qx, p.x, fmaf(qy, p.y, qz * p.z));
        unsigned key = fkey(fmaf(-2.f, dot, p.w));
        unsigned bin = key >> 24;
        if (bin < bin1) {
            unsigned pos = atomicAdd(&cnto[w], 1u);
            obase[pos] = j;
        } else if (bin == bin1) {
            unsigned pos = atomicAdd(&cntb[w], 1u);
            if (pos < BUFCAP) myb[pos] = ((unsigned long long)key << 32) | (unsigned)j;
        }
    }
    __syncwarp();

    const int kprime = KNB - (int)m1;           // >= 1 by construction
    const unsigned nb = cntb[w];

    if (nb <= BUFCAP) {
        // normal path: select kprime smallest (key,idx) from buffer
        unsigned long long v[NLOC];
#pragma unroll
        for (int u = 0; u < NLOC; u++) {
            int t = lane + u * 32;
            v[u] = (t < (int)nb) ? myb[t] : 0xffffffffffffffffull;
        }
        for (int r = 0; r < kprime; r++) {
            unsigned long long lmin = v[0]; int lpos = 0;
#pragma unroll
            for (int u = 1; u < NLOC; u++)
                if (v[u] < lmin) { lmin = v[u]; lpos = u; }
            unsigned long long wmin = lmin;
#pragma unroll
            for (int d = 16; d; d >>= 1) {
                unsigned long long o = __shfl_xor_sync(0xffffffffu, wmin, d);
                wmin = (o < wmin) ? o : wmin;
            }
            if (lmin == wmin) {
#pragma unroll
                for (int u = 0; u < NLOC; u++)
                    if (u == lpos) v[u] = 0xffffffffffffffffull;
            }
            if (lane == 0) obase[m1 + r] = (int)(unsigned)(wmin & 0xffffffffull);
        }
    } else {
        // overflow fallback (practically never): exact rescan selection
        unsigned long long last = 0;
        for (int r = 0; r < kprime; r++) {
            unsigned long long best = 0xffffffffffffffffull;
            for (int i = 0; i < NPTS / 32; i++) {
                int j = (i << 5) + lane;
                float4 p = pts[j];
                float dot = fmaf(qx, p.x, fmaf(qy, p.y, qz * p.z));
                unsigned key = fkey(fmaf(-2.f, dot, p.w));
                if ((key >> 24) == bin1) {
                    unsigned long long kk = ((unsigned long long)key << 32) | (unsigned)j;
                    if (kk > last && kk < best) best = kk;
                }
            }
#pragma unroll
            for (int d = 16; d; d >>= 1) {
                unsigned long long o = __shfl_xor_sync(0xffffffffu, best, d);
                best = (o < best) ? o : best;
            }
            if (lane == 0) obase[m1 + r] = (int)(unsigned)(best & 0xffffffffull);
            last = best;
        }
    }
}

// ---------------------------------------------------------------------------
// Fused main kernel (unchanged from round 2): feat gather -> y1 -> packed
// f32x2 GEMM (E x 384)@(384 x 64) -> BN+LReLU -> max over k -> 64->3 conv.
// ---------------------------------------------------------------------------
__global__ void __launch_bounds__(THR, 1) main_kernel(
    const float* __restrict__ x,    const float* __restrict__ b0,
    const float* __restrict__ b1,   const float* __restrict__ w_out,
    const float* __restrict__ g_out, const float* __restrict__ b_out,
    float* __restrict__ out)
{
    extern __shared__ float smem[];
    float* Wp  = smem;                 // 24576  Wp[kc][64]
    float* y1s = smem + 24576;         // 20480  y1s[m][320]
    float* fts = y1s + 20480;          //  1920  fts[c][320]
    float* x1s = fts + 1920;           //  1024  x1s[pt][64]
    float* w0f = x1s + 1024;           //   384
    float* b0s = w0f + 384;            //    64
    float* b1s = b0s + 64;             //    64

    const int tid = threadIdx.x;
    const int b   = blockIdx.x >> 8;
    const int p0  = (blockIdx.x & 255) * PTS;
    const float* xb = x + b * 3 * NPTS;

    // gather feat: [xj - xi ; xi]
    for (int e = tid; e < EDG; e += THR) {
        int p  = e / KNB;
        int kk = e - p * KNB;
        int n  = p0 + p;
        int j  = g_idx[(b * NPTS + n) * KNB + kk];
        float xi0 = xb[n],          xi1 = xb[NPTS + n],  xi2 = xb[2 * NPTS + n];
        float xj0 = xb[j],          xj1 = xb[NPTS + j],  xj2 = xb[2 * NPTS + j];
        fts[0 * EDG + e] = xj0 - xi0;
        fts[1 * EDG + e] = xj1 - xi1;
        fts[2 * EDG + e] = xj2 - xi2;
        fts[3 * EDG + e] = xi0;
        fts[4 * EDG + e] = xi1;
        fts[5 * EDG + e] = xi2;
    }

    {
        const float4* src = reinterpret_cast<const float4*>(g_wp);
        float4* dst = reinterpret_cast<float4*>(Wp);
#pragma unroll
        for (int i = 0; i < 24; i++) dst[tid + i * THR] = src[tid + i * THR];
    }
    for (int i = tid; i < 384; i += THR) w0f[i] = g_w0f[i];
    if (tid < 64) { b0s[tid] = b0[tid]; b1s[tid] = b1[tid]; }
    __syncthreads();

    // y1 = lrelu(w0f @ feat + b0)
    for (int i = tid; i < 64 * EDG; i += THR) {
        int m = i / EDG;
        int e = i - m * EDG;
        const float* wr = w0f + m * 6;
        float v = b0s[m];
        v = fmaf(wr[0], fts[e],           v);
        v = fmaf(wr[1], fts[EDG + e],     v);
        v = fmaf(wr[2], fts[2 * EDG + e], v);
        v = fmaf(wr[3], fts[3 * EDG + e], v);
        v = fmaf(wr[4], fts[4 * EDG + e], v);
        v = fmaf(wr[5], fts[5 * EDG + e], v);
        y1s[i] = lrelu(v);
    }
    __syncthreads();

    const int og = tid & 7;
    const int eg = tid >> 3;
    const int e0 = eg * 10;
    const int o0 = og * 8;

    float2 acc[5][8];
#pragma unroll
    for (int i = 0; i < 5; i++)
#pragma unroll
        for (int j = 0; j < 8; j++) acc[i][j] = make_float2(0.f, 0.f);

#pragma unroll 1
    for (int m = 0; m < 64; m++) {
        float2 yp[5];
        const float* yr = y1s + m * EDG + e0;
#pragma unroll
        for (int i = 0; i < 5; i++)
            yp[i] = *reinterpret_cast<const float2*>(yr + 2 * i);
#pragma unroll
        for (int c = 0; c < 6; c++) {
            const float* wr = Wp + (m * 6 + c) * 64 + o0;
            float4 wa = *reinterpret_cast<const float4*>(wr);
            float4 wb = *reinterpret_cast<const float4*>(wr + 4);
            float2 wd[8];
            wd[0] = make_float2(wa.x, wa.x); wd[1] = make_float2(wa.y, wa.y);
            wd[2] = make_float2(wa.z, wa.z); wd[3] = make_float2(wa.w, wa.w);
            wd[4] = make_float2(wb.x, wb.x); wd[5] = make_float2(wb.y, wb.y);
            wd[6] = make_float2(wb.z, wb.z); wd[7] = make_float2(wb.w, wb.w);
            const float* fr = fts + c * EDG + e0;
#pragma unroll
            for (int i = 0; i < 5; i++) {
                float2 fp = *reinterpret_cast<const float2*>(fr + 2 * i);
                float2 a  = fmul2(yp[i], fp);
#pragma unroll
                for (int j = 0; j < 8; j++)
                    acc[i][j] = ffma2(a, wd[j], acc[i][j]);
            }
        }
    }

    float pmax[8];
#pragma unroll
    for (int j = 0; j < 8; j++) pmax[j] = -3.4e38f;
#pragma unroll
    for (int j = 0; j < 8; j++) {
        float bb = b1s[o0 + j];
#pragma unroll
        for (int i = 0; i < 5; i++) {
            float vx = lrelu(acc[i][j].x + bb);
            float vy = lrelu(acc[i][j].y + bb);
            pmax[j] = fmaxf(pmax[j], fmaxf(vx, vy));
        }
    }
    const int pt = eg >> 1;
    if ((eg & 1) == 0) {
#pragma unroll
        for (int j = 0; j < 8; j++) x1s[pt * 64 + o0 + j] = pmax[j];
    }
    __syncthreads();
    if (eg & 1) {
#pragma unroll
        for (int j = 0; j < 8; j++) {
            float* p = x1s + pt * 64 + o0 + j;
            *p = fmaxf(*p, pmax[j]);
        }
    }
    __syncthreads();

    if (tid < 48) {
        int oo  = tid >> 4;
        int pt2 = tid & 15;
        const float* wr = w_out + oo * 64;
        const float* xr = x1s + pt2 * 64;
        float s = 0.f;
#pragma unroll
        for (int o = 0; o < 64; o++) s = fmaf(wr[o], xr[o], s);
        float v = s * (g_out[oo] * rsqrtf(1.f + EPSV)) + b_out[oo];
        out[(b * 3 + oo) * NPTS + p0 + pt2] = lrelu(v);
    }
}

// ---------------------------------------------------------------------------
extern "C" void kernel_launch(void* const* d_in, const int* in_sizes, int n_in,
                              void* d_out, int out_size) {
    const float* x     = (const float*)d_in[0];
    const float* w0    = (const float*)d_in[1];
    const float* g0    = (const float*)d_in[2];
    const float* b0    = (const float*)d_in[3];
    const float* w1    = (const float*)d_in[4];
    const float* g1    = (const float*)d_in[5];
    const float* b1    = (const float*)d_in[6];
    const float* w_out = (const float*)d_in[7];
    const float* g_out = (const float*)d_in[8];
    const float* b_out = (const float*)d_in[9];
    float* out = (float*)d_out;

    const int knn_smem  = 65536 + 8192 + 24576 + 64;                       // 98368
    const int main_smem = (24576 + 20480 + 1920 + 1024 + 384 + 64 + 64) * 4;

    cudaFuncSetAttribute(knn_prep_kernel, cudaFuncAttributeMaxDynamicSharedMemorySize,
                         knn_smem);
    cudaFuncSetAttribute(main_kernel, cudaFuncAttributeMaxDynamicSharedMemorySize,
                         main_smem);

    knn_prep_kernel<<<dim3(NPTS / QPW, BATCH), 256, knn_smem>>>(x, w0, g0, w1, g1);
    main_kernel<<<BATCH * (NPTS / PTS), THR, main_smem>>>(x, b0, b1, w_out,
                                                          g_out, b_out, out);
}

// round 4
// speedup vs baseline: 1.7313x; 1.7313x over previous
#include <cuda_runtime.h>

#define BATCH 4
#define NPTS  4096
#define KNB   20
#define EPSV  1e-5f
#define SLOPE 0.2f

#define PTS 16              // points per block (main kernel)
#define EDG (PTS * KNB)     // 320 edges per block
#define THR 256

#define QPW 8               // queries (=warps) per knn block
#define BUFCAP 256          // boundary-subbin buffer capacity per warp
#define NLOC (BUFCAP / 32)

// scratch (device globals; no allocations allowed)
__device__ float g_wp[384 * 64];          // reindexed + s1-folded w1: Wp[m*6+c][o]
__device__ float g_w0f[384];              // s0-folded w0
__device__ int   g_idx[BATCH * NPTS * KNB];

__device__ __forceinline__ float lrelu(float v) { return fmaxf(v, SLOPE * v); }

__device__ __forceinline__ float2 ffma2(float2 a, float2 b, float2 c) {
    float2 d;
    asm("fma.rn.f32x2 %0, %1, %2, %3;"
        : "=l"(reinterpret_cast<unsigned long long&>(d))
        : "l"(reinterpret_cast<unsigned long long&>(a)),
          "l"(reinterpret_cast<unsigned long long&>(b)),
          "l"(reinterpret_cast<unsigned long long&>(c)));
    return d;
}
__device__ __forceinline__ float2 fmul2(float2 a, float2 b) {
    float2 d;
    asm("mul.rn.f32x2 %0, %1, %2;"
        : "=l"(reinterpret_cast<unsigned long long&>(d))
        : "l"(reinterpret_cast<unsigned long long&>(a)),
          "l"(reinterpret_cast<unsigned long long&>(b)));
    return d;
}

// monotone float -> uint key (total order, incl. negatives)
__device__ __forceinline__ unsigned fkey(float d) {
    unsigned b = __float_as_uint(d);
    return b ^ ((unsigned)((int)b >> 31) | 0x80000000u);
}

// warp scan over 256-bin hist (lane owns bins lane*8..lane*8+7):
// find first bin where cumulative >= K; return bin and count strictly below.
__device__ __forceinline__ void scan_find(const unsigned* myh, int lane, unsigned K,
                                          unsigned& bsel, unsigned& mbelow) {
    unsigned s = 0;
#pragma unroll
    for (int j = 0; j < 8; j++) s += myh[lane * 8 + j];
    unsigned incl = s;
#pragma unroll
    for (int d = 1; d < 32; d <<= 1) {
        unsigned t = __shfl_up_sync(0xffffffffu, incl, d);
        if (lane >= d) incl += t;
    }
    unsigned excl = incl - s;
    unsigned bal  = __ballot_sync(0xffffffffu, incl >= K);
    int L = __ffs(bal) - 1;
    unsigned bl = 0, ml = 0;
    if (lane == L) {
        unsigned cum = excl;
#pragma unroll
        for (int j = 0; j < 8; j++) {
            unsigned h = myh[lane * 8 + j];
            if (cum + h >= K) { bl = lane * 8 + j; ml = cum; break; }
            cum += h;
        }
    }
    bsel   = __shfl_sync(0xffffffffu, bl, L);
    mbelow = __shfl_sync(0xffffffffu, ml, L);
}

// ---------------------------------------------------------------------------
// KNN via adaptive 2-level linear-histogram select (warp per query) + prep.
// Grid (NPTS/QPW, BATCH) = (512, 4), 256 threads (8 warps), 2 blocks/SM.
// d = ||p||^2 - 2 q.p (constant ||q||^2 shift preserves ordering; self point
// minimal, included — same selection as reference top_k on -||q-p||^2).
// Pass A: dmin/dmax. Pass B: 256 linear bins -> boundary b1, m1(<20).
// Pass C: 256 sub-bins inside b1 -> b2, m2. Pass D: below-boundary -> g_idx
// directly (set semantics; downstream is max over k); boundary sub-bin ->
// u64 buffer; select remaining 20-m1-m2 by repeated warp-min (exact,
// deterministic, ties -> lowest index).
// ---------------------------------------------------------------------------
__global__ void __launch_bounds__(256, 2) knn_prep_kernel(
    const float* __restrict__ x,
    const float* __restrict__ w0, const float* __restrict__ g0,
    const float* __restrict__ w1, const float* __restrict__ g1)
{
    extern __shared__ char dsm[];
    float4*             pts  = reinterpret_cast<float4*>(dsm);                    // 65536
    unsigned*           hist = reinterpret_cast<unsigned*>(dsm + 65536);          //  8192
    unsigned long long* buf  = reinterpret_cast<unsigned long long*>(dsm + 73728);// 16384
    unsigned*           cnt  = reinterpret_cast<unsigned*>(dsm + 90112);          //    64

    const int tid  = threadIdx.x;
    const int lane = tid & 31;
    const int w    = tid >> 5;
    const int b    = blockIdx.y;
    const int q    = blockIdx.x * QPW + w;
    const float* xb = x + b * 3 * NPTS;

    // ---- prep: distributed over the 2048 blocks ----
    {
        const int gt = (blockIdx.y * gridDim.x + blockIdx.x) * 256 + tid;
        const float inv = rsqrtf(1.f + EPSV);
        if (gt < 384) g_w0f[gt] = w0[gt] * g0[gt / 6] * inv;
        if (gt < 384 * 64) {
            int o  = gt & 63;
            int kc = gt >> 6;
            int m  = kc / 6;
            int c  = kc - m * 6;
            g_wp[gt] = g1[o] * inv * w1[(o * 6 + c) * 64 + m];
        }
    }

    // ---- stage batch points (x,y,z,||p||^2) ----
    for (int i = tid; i < NPTS; i += 256) {
        float vx = xb[i], vy = xb[NPTS + i], vz = xb[2 * NPTS + i];
        pts[i] = make_float4(vx, vy, vz, fmaf(vx, vx, fmaf(vy, vy, vz * vz)));
    }
    if (tid < 16) cnt[tid] = 0;
    __syncthreads();

    const float4 qp = pts[q];
    const float qx = qp.x, qy = qp.y, qz = qp.z;
    unsigned* myh = hist + (w << 8);

    // ---- pass A: dmin / dmax ----
    float dmin = __int_as_float(0x7f800000);
    float dmax = -dmin;
    for (int i = 0; i < NPTS / 32; i++) {
        float4 p = pts[(i << 5) + lane];
        float dot = fmaf(qx, p.x, fmaf(qy, p.y, qz * p.z));
        float d   = fmaf(-2.f, dot, p.w);
        dmin = fminf(dmin, d);
        dmax = fmaxf(dmax, d);
    }
#pragma unroll
    for (int o = 16; o; o >>= 1) {
        dmin = fminf(dmin, __shfl_xor_sync(0xffffffffu, dmin, o));
        dmax = fmaxf(dmax, __shfl_xor_sync(0xffffffffu, dmax, o));
    }
    const float width  = fmaxf(dmax - dmin, 1e-30f);
    const float scale1 = 256.f / width;

    // ---- pass B: level-1 histogram (256 linear bins over [dmin,dmax]) ----
#pragma unroll
    for (int j = 0; j < 8; j++) myh[lane * 8 + j] = 0;
    __syncwarp();
    for (int i = 0; i < NPTS / 32; i++) {
        float4 p = pts[(i << 5) + lane];
        float dot = fmaf(qx, p.x, fmaf(qy, p.y, qz * p.z));
        float d   = fmaf(-2.f, dot, p.w);
        int t1 = min(255, (int)((d - dmin) * scale1));
        unsigned msk = __match_any_sync(0xffffffffu, (unsigned)t1);
        if (lane == (__ffs(msk) - 1)) atomicAdd(&myh[t1], __popc(msk));
    }
    __syncwarp();
    unsigned b1, m1;
    scan_find(myh, lane, KNB, b1, m1);
    const float b1f = (float)b1;

    // ---- pass C: level-2 histogram (256 sub-bins inside bin b1) ----
#pragma unroll
    for (int j = 0; j < 8; j++) myh[lane * 8 + j] = 0;
    __syncwarp();
    for (int i = 0; i < NPTS / 32; i++) {
        float4 p = pts[(i << 5) + lane];
        float dot = fmaf(qx, p.x, fmaf(qy, p.y, qz * p.z));
        float d   = fmaf(-2.f, dot, p.w);
        float t   = (d - dmin) * scale1;
        int t1 = min(255, (int)t);
        unsigned v = 0xffffffffu;                       // sentinel: not in b1
        if (t1 == (int)b1) v = (unsigned)min(255, (int)((t - b1f) * 256.f));
        unsigned msk = __match_any_sync(0xffffffffu, v);
        if (v != 0xffffffffu && lane == (__ffs(msk) - 1)) atomicAdd(&myh[v], __popc(msk));
    }
    __syncwarp();
    unsigned b2, m2;
    scan_find(myh, lane, KNB - m1, b2, m2);

    // ---- pass D: emit ----
    int* obase = g_idx + (b * NPTS + q) * KNB;
    unsigned long long* myb = buf + w * BUFCAP;
    unsigned* cnto = cnt + w;
    unsigned* cntb = cnt + 8 + w;
    for (int i = 0; i < NPTS / 32; i++) {
        int j = (i << 5) + lane;
        float4 p = pts[j];
        float dot = fmaf(qx, p.x, fmaf(qy, p.y, qz * p.z));
        float d   = fmaf(-2.f, dot, p.w);
        float t   = (d - dmin) * scale1;
        int t1 = min(255, (int)t);
        if (t1 < (int)b1) {
            unsigned pos = atomicAdd(cnto, 1u);
            obase[pos] = j;
        } else if (t1 == (int)b1) {
            int t2 = min(255, (int)((t - b1f) * 256.f));
            if (t2 < (int)b2) {
                unsigned pos = atomicAdd(cnto, 1u);
                obase[pos] = j;
            } else if (t2 == (int)b2) {
                unsigned pos = atomicAdd(cntb, 1u);
                if (pos < BUFCAP)
                    myb[pos] = ((unsigned long long)fkey(d) << 32) | (unsigned)j;
            }
        }
    }
    __syncwarp();

    const int kprime  = KNB - (int)m1 - (int)m2;        // >= 1 by construction
    const unsigned nb = *cntb;
    const unsigned ob = m1 + m2;

    if (nb <= BUFCAP) {
        unsigned long long v[NLOC];
#pragma unroll
        for (int u = 0; u < NLOC; u++) {
            int t = lane + u * 32;
            v[u] = (t < (int)nb) ? myb[t] : 0xffffffffffffffffull;
        }
        for (int r = 0; r < kprime; r++) {
            unsigned long long lmin = v[0]; int lpos = 0;
#pragma unroll
            for (int u = 1; u < NLOC; u++)
                if (v[u] < lmin) { lmin = v[u]; lpos = u; }
            unsigned long long wmin = lmin;
#pragma unroll
            for (int d = 16; d; d >>= 1) {
                unsigned long long o = __shfl_xor_sync(0xffffffffu, wmin, d);
                wmin = (o < wmin) ? o : wmin;
            }
            if (lmin == wmin) {
#pragma unroll
                for (int u = 0; u < NLOC; u++)
                    if (u == lpos) v[u] = 0xffffffffffffffffull;
            }
            if (lane == 0) obase[ob + r] = (int)(unsigned)(wmin & 0xffffffffull);
        }
    } else {
        // pathological fallback: exact rescan restricted to boundary sub-bin
        unsigned long long last = 0;
        for (int r = 0; r < kprime; r++) {
            unsigned long long best = 0xffffffffffffffffull;
            for (int i = 0; i < NPTS / 32; i++) {
                int j = (i << 5) + lane;
                float4 p = pts[j];
                float dot = fmaf(qx, p.x, fmaf(qy, p.y, qz * p.z));
                float d   = fmaf(-2.f, dot, p.w);
                float t   = (d - dmin) * scale1;
                int t1 = min(255, (int)t);
                if (t1 == (int)b1) {
                    int t2 = min(255, (int)((t - b1f) * 256.f));
                    if (t2 == (int)b2) {
                        unsigned long long kk =
                            ((unsigned long long)fkey(d) << 32) | (unsigned)j;
                        if (kk > last && kk < best) best = kk;
                    }
                }
            }
#pragma unroll
            for (int d = 16; d; d >>= 1) {
                unsigned long long o = __shfl_xor_sync(0xffffffffu, best, d);
                best = (o < best) ? o : best;
            }
            if (lane == 0) obase[ob + r] = (int)(unsigned)(best & 0xffffffffull);
            last = best;
        }
    }
}

// ---------------------------------------------------------------------------
// Fused main kernel (unchanged, 329us @ fma 70.5%): feat gather -> y1 ->
// packed f32x2 GEMM (E x 384)@(384 x 64) -> BN+LReLU -> max k -> 64->3 conv.
// ---------------------------------------------------------------------------
__global__ void __launch_bounds__(THR, 1) main_kernel(
    const float* __restrict__ x,    const float* __restrict__ b0,
    const float* __restrict__ b1,   const float* __restrict__ w_out,
    const float* __restrict__ g_out, const float* __restrict__ b_out,
    float* __restrict__ out)
{
    extern __shared__ float smem[];
    float* Wp  = smem;                 // 24576  Wp[kc][64]
    float* y1s = smem + 24576;         // 20480  y1s[m][320]
    float* fts = y1s + 20480;          //  1920  fts[c][320]
    float* x1s = fts + 1920;           //  1024  x1s[pt][64]
    float* w0f = x1s + 1024;           //   384
    float* b0s = w0f + 384;            //    64
    float* b1s = b0s + 64;             //    64

    const int tid = threadIdx.x;
    const int b   = blockIdx.x >> 8;
    const int p0  = (blockIdx.x & 255) * PTS;
    const float* xb = x + b * 3 * NPTS;

    for (int e = tid; e < EDG; e += THR) {
        int p  = e / KNB;
        int kk = e - p * KNB;
        int n  = p0 + p;
        int j  = g_idx[(b * NPTS + n) * KNB + kk];
        float xi0 = xb[n],          xi1 = xb[NPTS + n],  xi2 = xb[2 * NPTS + n];
        float xj0 = xb[j],          xj1 = xb[NPTS + j],  xj2 = xb[2 * NPTS + j];
        fts[0 * EDG + e] = xj0 - xi0;
        fts[1 * EDG + e] = xj1 - xi1;
        fts[2 * EDG + e] = xj2 - xi2;
        fts[3 * EDG + e] = xi0;
        fts[4 * EDG + e] = xi1;
        fts[5 * EDG + e] = xi2;
    }

    {
        const float4* src = reinterpret_cast<const float4*>(g_wp);
        float4* dst = reinterpret_cast<float4*>(Wp);
#pragma unroll
        for (int i = 0; i < 24; i++) dst[tid + i * THR] = src[tid + i * THR];
    }
    for (int i = tid; i < 384; i += THR) w0f[i] = g_w0f[i];
    if (tid < 64) { b0s[tid] = b0[tid]; b1s[tid] = b1[tid]; }
    __syncthreads();

    for (int i = tid; i < 64 * EDG; i += THR) {
        int m = i / EDG;
        int e = i - m * EDG;
        const float* wr = w0f + m * 6;
        float v = b0s[m];
        v = fmaf(wr[0], fts[e],           v);
        v = fmaf(wr[1], fts[EDG + e],     v);
        v = fmaf(wr[2], fts[2 * EDG + e], v);
        v = fmaf(wr[3], fts[3 * EDG + e], v);
        v = fmaf(wr[4], fts[4 * EDG + e], v);
        v = fmaf(wr[5], fts[5 * EDG + e], v);
        y1s[i] = lrelu(v);
    }
    __syncthreads();

    const int og = tid & 7;
    const int eg = tid >> 3;
    const int e0 = eg * 10;
    const int o0 = og * 8;

    float2 acc[5][8];
#pragma unroll
    for (int i = 0; i < 5; i++)
#pragma unroll
        for (int j = 0; j < 8; j++) acc[i][j] = make_float2(0.f, 0.f);

#pragma unroll 1
    for (int m = 0; m < 64; m++) {
        float2 yp[5];
        const float* yr = y1s + m * EDG + e0;
#pragma unroll
        for (int i = 0; i < 5; i++)
            yp[i] = *reinterpret_cast<const float2*>(yr + 2 * i);
#pragma unroll
        for (int c = 0; c < 6; c++) {
            const float* wr = Wp + (m * 6 + c) * 64 + o0;
            float4 wa = *reinterpret_cast<const float4*>(wr);
            float4 wb = *reinterpret_cast<const float4*>(wr + 4);
            float2 wd[8];
            wd[0] = make_float2(wa.x, wa.x); wd[1] = make_float2(wa.y, wa.y);
            wd[2] = make_float2(wa.z, wa.z); wd[3] = make_float2(wa.w, wa.w);
            wd[4] = make_float2(wb.x, wb.x); wd[5] = make_float2(wb.y, wb.y);
            wd[6] = make_float2(wb.z, wb.z); wd[7] = make_float2(wb.w, wb.w);
            const float* fr = fts + c * EDG + e0;
#pragma unroll
            for (int i = 0; i < 5; i++) {
                float2 fp = *reinterpret_cast<const float2*>(fr + 2 * i);
                float2 a  = fmul2(yp[i], fp);
#pragma unroll
                for (int j = 0; j < 8; j++)
                    acc[i][j] = ffma2(a, wd[j], acc[i][j]);
            }
        }
    }

    float pmax[8];
#pragma unroll
    for (int j = 0; j < 8; j++) pmax[j] = -3.4e38f;
#pragma unroll
    for (int j = 0; j < 8; j++) {
        float bb = b1s[o0 + j];
#pragma unroll
        for (int i = 0; i < 5; i++) {
            float vx = lrelu(acc[i][j].x + bb);
            float vy = lrelu(acc[i][j].y + bb);
            pmax[j] = fmaxf(pmax[j], fmaxf(vx, vy));
        }
    }
    const int pt = eg >> 1;
    if ((eg & 1) == 0) {
#pragma unroll
        for (int j = 0; j < 8; j++) x1s[pt * 64 + o0 + j] = pmax[j];
    }
    __syncthreads();
    if (eg & 1) {
#pragma unroll
        for (int j = 0; j < 8; j++) {
            float* p = x1s + pt * 64 + o0 + j;
            *p = fmaxf(*p, pmax[j]);
        }
    }
    __syncthreads();

    if (tid < 48) {
        int oo  = tid >> 4;
        int pt2 = tid & 15;
        const float* wr = w_out + oo * 64;
        const float* xr = x1s + pt2 * 64;
        float s = 0.f;
#pragma unroll
        for (int o = 0; o < 64; o++) s = fmaf(wr[o], xr[o], s);
        float v = s * (g_out[oo] * rsqrtf(1.f + EPSV)) + b_out[oo];
        out[(b * 3 + oo) * NPTS + p0 + pt2] = lrelu(v);
    }
}

// ---------------------------------------------------------------------------
extern "C" void kernel_launch(void* const* d_in, const int* in_sizes, int n_in,
                              void* d_out, int out_size) {
    const float* x     = (const float*)d_in[0];
    const float* w0    = (const float*)d_in[1];
    const float* g0    = (const float*)d_in[2];
    const float* b0    = (const float*)d_in[3];
    const float* w1    = (const float*)d_in[4];
    const float* g1    = (const float*)d_in[5];
    const float* b1    = (const float*)d_in[6];
    const float* w_out = (const float*)d_in[7];
    const float* g_out = (const float*)d_in[8];
    const float* b_out = (const float*)d_in[9];
    float* out = (float*)d_out;

    const int knn_smem  = 65536 + 8192 + 16384 + 64;                       // 90176
    const int main_smem = (24576 + 20480 + 1920 + 1024 + 384 + 64 + 64) * 4;

    cudaFuncSetAttribute(knn_prep_kernel, cudaFuncAttributeMaxDynamicSharedMemorySize,
                         knn_smem);
    cudaFuncSetAttribute(main_kernel, cudaFuncAttributeMaxDynamicSharedMemorySize,
                         main_smem);

    knn_prep_kernel<<<dim3(NPTS / QPW, BATCH), 256, knn_smem>>>(x, w0, g0, w1, g1);
    main_kernel<<<BATCH * (NPTS / PTS), THR, main_smem>>>(x, b0, b1, w_out,
                                                          g_out, b_out, out);
}

// round 5
// speedup vs baseline: 2.2476x; 1.2982x over previous
#include <cuda_runtime.h>

#define BATCH 4
#define NPTS  4096
#define KNB   20
#define EPSV  1e-5f
#define SLOPE 0.2f

#define PTS 16              // points per block (main kernel)
#define EDG (PTS * KNB)     // 320 edges per block
#define THR 256

#define QPB 8               // queries (= warps) per knn block

// scratch (device globals; no allocations allowed)
__device__ float g_wp[384 * 64];          // reindexed + s1-folded w1: Wp[m*6+c][o]
__device__ float g_w0f[384];              // s0-folded w0
__device__ int   g_idx[BATCH * NPTS * KNB];

__device__ __forceinline__ float lrelu(float v) { return fmaxf(v, SLOPE * v); }

__device__ __forceinline__ float2 ffma2(float2 a, float2 b, float2 c) {
    float2 d;
    asm("fma.rn.f32x2 %0, %1, %2, %3;"
        : "=l"(reinterpret_cast<unsigned long long&>(d))
        : "l"(reinterpret_cast<unsigned long long&>(a)),
          "l"(reinterpret_cast<unsigned long long&>(b)),
          "l"(reinterpret_cast<unsigned long long&>(c)));
    return d;
}
__device__ __forceinline__ float2 fmul2(float2 a, float2 b) {
    float2 d;
    asm("mul.rn.f32x2 %0, %1, %2;"
        : "=l"(reinterpret_cast<unsigned long long&>(d))
        : "l"(reinterpret_cast<unsigned long long&>(a)),
          "l"(reinterpret_cast<unsigned long long&>(b)));
    return d;
}

// monotone float -> uint key (total order, incl. negatives)
__device__ __forceinline__ unsigned fkey(float d) {
    unsigned b = __float_as_uint(d);
    return b ^ ((unsigned)((int)b >> 31) | 0x80000000u);
}

// ---------------------------------------------------------------------------
// KNN: warp per query + fused weight prep.
// Grid (NPTS/QPB, BATCH) = (512, 4), 256 threads (8 warps), 2 blocks/SM.
// Each lane scans the strided subset {t*32+lane : t in [0,128)} keeping an
// unsorted register top-20 with worst-tracking (d = ||p||^2 - 2 q.p; the
// constant ||q||^2 shift preserves ordering vs reference's -||q-p||^2; self
// point minimal, included — identical selection to rounds 1-2 which matched).
// Lane subsets are disjoint, so the union of lane top-20s contains the global
// top-20; exact extraction by 20 rounds of warp-min over packed (key,idx) u64
// (deterministic, ties -> lowest index). Output order irrelevant downstream.
// ---------------------------------------------------------------------------
__global__ void __launch_bounds__(256, 2) knn_prep_kernel(
    const float* __restrict__ x,
    const float* __restrict__ w0, const float* __restrict__ g0,
    const float* __restrict__ w1, const float* __restrict__ g1)
{
    extern __shared__ float4 pts[];          // 4096 * 16 = 65536 bytes

    const int tid  = threadIdx.x;
    const int lane = tid & 31;
    const int w    = tid >> 5;
    const int b    = blockIdx.y;
    const int q    = blockIdx.x * QPB + w;
    const float* xb = x + b * 3 * NPTS;

    // ---- prep: distributed over the 2048 blocks ----
    {
        const int gt = (blockIdx.y * gridDim.x + blockIdx.x) * 256 + tid;
        const float inv = rsqrtf(1.f + EPSV);
        if (gt < 384) g_w0f[gt] = w0[gt] * g0[gt / 6] * inv;
        if (gt < 384 * 64) {
            int o  = gt & 63;
            int kc = gt >> 6;
            int m  = kc / 6;
            int c  = kc - m * 6;
            g_wp[gt] = g1[o] * inv * w1[(o * 6 + c) * 64 + m];
        }
    }

    // ---- stage batch points (x,y,z,||p||^2) ----
    for (int i = tid; i < NPTS; i += 256) {
        float vx = xb[i], vy = xb[NPTS + i], vz = xb[2 * NPTS + i];
        pts[i] = make_float4(vx, vy, vz, fmaf(vx, vx, fmaf(vy, vy, vz * vz)));
    }
    __syncthreads();

    const float4 qp = pts[q];
    const float qx = qp.x, qy = qp.y, qz = qp.z;

    // ---- per-lane insertion top-20 over 128 strided candidates ----
    float nd[KNB];
    int   ni[KNB];
#pragma unroll
    for (int i = 0; i < KNB; i++) { nd[i] = __int_as_float(0x7f800000); ni[i] = 0; }
    float worst = __int_as_float(0x7f800000);
    int   wpos  = 0;

#pragma unroll 4
    for (int t = 0; t < NPTS / 32; t++) {
        const int j = (t << 5) + lane;
        float4 p  = pts[j];
        float dot = fmaf(qx, p.x, fmaf(qy, p.y, qz * p.z));
        float d   = fmaf(-2.f, dot, p.w);
        if (d < worst) {
            nd[wpos] = d; ni[wpos] = j;
            worst = nd[0]; wpos = 0;
#pragma unroll
            for (int i = 1; i < KNB; i++)
                if (nd[i] > worst) { worst = nd[i]; wpos = i; }
        }
    }

    // ---- exact warp merge: 20 rounds of min-extract over packed u64 ----
    unsigned long long v[KNB];
#pragma unroll
    for (int i = 0; i < KNB; i++)
        v[i] = ((unsigned long long)fkey(nd[i]) << 32) | (unsigned)ni[i];

    int* obase = g_idx + (b * NPTS + q) * KNB;
    for (int r = 0; r < KNB; r++) {
        unsigned long long lmin = v[0]; int lpos = 0;
#pragma unroll
        for (int u = 1; u < KNB; u++)
            if (v[u] < lmin) { lmin = v[u]; lpos = u; }
        unsigned long long wmin = lmin;
#pragma unroll
        for (int d = 16; d; d >>= 1) {
            unsigned long long o = __shfl_xor_sync(0xffffffffu, wmin, d);
            wmin = (o < wmin) ? o : wmin;
        }
        if (lmin == wmin) {
#pragma unroll
            for (int u = 0; u < KNB; u++)
                if (u == lpos) v[u] = 0xffffffffffffffffull;
        }
        if (lane == 0) obase[r] = (int)(unsigned)(wmin & 0xffffffffull);
    }
}

// ---------------------------------------------------------------------------
// Fused main kernel (unchanged, 329us @ fma 70.5%): feat gather -> y1 ->
// packed f32x2 GEMM (E x 384)@(384 x 64) -> BN+LReLU -> max k -> 64->3 conv.
// ---------------------------------------------------------------------------
__global__ void __launch_bounds__(THR, 1) main_kernel(
    const float* __restrict__ x,    const float* __restrict__ b0,
    const float* __restrict__ b1,   const float* __restrict__ w_out,
    const float* __restrict__ g_out, const float* __restrict__ b_out,
    float* __restrict__ out)
{
    extern __shared__ float smem[];
    float* Wp  = smem;                 // 24576  Wp[kc][64]
    float* y1s = smem + 24576;         // 20480  y1s[m][320]
    float* fts = y1s + 20480;          //  1920  fts[c][320]
    float* x1s = fts + 1920;           //  1024  x1s[pt][64]
    float* w0f = x1s + 1024;           //   384
    float* b0s = w0f + 384;            //    64
    float* b1s = b0s + 64;             //    64

    const int tid = threadIdx.x;
    const int b   = blockIdx.x >> 8;
    const int p0  = (blockIdx.x & 255) * PTS;
    const float* xb = x + b * 3 * NPTS;

    for (int e = tid; e < EDG; e += THR) {
        int p  = e / KNB;
        int kk = e - p * KNB;
        int n  = p0 + p;
        int j  = g_idx[(b * NPTS + n) * KNB + kk];
        float xi0 = xb[n],          xi1 = xb[NPTS + n],  xi2 = xb[2 * NPTS + n];
        float xj0 = xb[j],          xj1 = xb[NPTS + j],  xj2 = xb[2 * NPTS + j];
        fts[0 * EDG + e] = xj0 - xi0;
        fts[1 * EDG + e] = xj1 - xi1;
        fts[2 * EDG + e] = xj2 - xi2;
        fts[3 * EDG + e] = xi0;
        fts[4 * EDG + e] = xi1;
        fts[5 * EDG + e] = xi2;
    }

    {
        const float4* src = reinterpret_cast<const float4*>(g_wp);
        float4* dst = reinterpret_cast<float4*>(Wp);
#pragma unroll
        for (int i = 0; i < 24; i++) dst[tid + i * THR] = src[tid + i * THR];
    }
    for (int i = tid; i < 384; i += THR) w0f[i] = g_w0f[i];
    if (tid < 64) { b0s[tid] = b0[tid]; b1s[tid] = b1[tid]; }
    __syncthreads();

    for (int i = tid; i < 64 * EDG; i += THR) {
        int m = i / EDG;
        int e = i - m * EDG;
        const float* wr = w0f + m * 6;
        float v = b0s[m];
        v = fmaf(wr[0], fts[e],           v);
        v = fmaf(wr[1], fts[EDG + e],     v);
        v = fmaf(wr[2], fts[2 * EDG + e], v);
        v = fmaf(wr[3], fts[3 * EDG + e], v);
        v = fmaf(wr[4], fts[4 * EDG + e], v);
        v = fmaf(wr[5], fts[5 * EDG + e], v);
        y1s[i] = lrelu(v);
    }
    __syncthreads();

    const int og = tid & 7;
    const int eg = tid >> 3;
    const int e0 = eg * 10;
    const int o0 = og * 8;

    float2 acc[5][8];
#pragma unroll
    for (int i = 0; i < 5; i++)
#pragma unroll
        for (int j = 0; j < 8; j++) acc[i][j] = make_float2(0.f, 0.f);

#pragma unroll 1
    for (int m = 0; m < 64; m++) {
        float2 yp[5];
        const float* yr = y1s + m * EDG + e0;
#pragma unroll
        for (int i = 0; i < 5; i++)
            yp[i] = *reinterpret_cast<const float2*>(yr + 2 * i);
#pragma unroll
        for (int c = 0; c < 6; c++) {
            const float* wr = Wp + (m * 6 + c) * 64 + o0;
            float4 wa = *reinterpret_cast<const float4*>(wr);
            float4 wb = *reinterpret_cast<const float4*>(wr + 4);
            float2 wd[8];
            wd[0] = make_float2(wa.x, wa.x); wd[1] = make_float2(wa.y, wa.y);
            wd[2] = make_float2(wa.z, wa.z); wd[3] = make_float2(wa.w, wa.w);
            wd[4] = make_float2(wb.x, wb.x); wd[5] = make_float2(wb.y, wb.y);
            wd[6] = make_float2(wb.z, wb.z); wd[7] = make_float2(wb.w, wb.w);
            const float* fr = fts + c * EDG + e0;
#pragma unroll
            for (int i = 0; i < 5; i++) {
                float2 fp = *reinterpret_cast<const float2*>(fr + 2 * i);
                float2 a  = fmul2(yp[i], fp);
#pragma unroll
                for (int j = 0; j < 8; j++)
                    acc[i][j] = ffma2(a, wd[j], acc[i][j]);
            }
        }
    }

    float pmax[8];
#pragma unroll
    for (int j = 0; j < 8; j++) pmax[j] = -3.4e38f;
#pragma unroll
    for (int j = 0; j < 8; j++) {
        float bb = b1s[o0 + j];
#pragma unroll
        for (int i = 0; i < 5; i++) {
            float vx = lrelu(acc[i][j].x + bb);
            float vy = lrelu(acc[i][j].y + bb);
            pmax[j] = fmaxf(pmax[j], fmaxf(vx, vy));
        }
    }
    const int pt = eg >> 1;
    if ((eg & 1) == 0) {
#pragma unroll
        for (int j = 0; j < 8; j++) x1s[pt * 64 + o0 + j] = pmax[j];
    }
    __syncthreads();
    if (eg & 1) {
#pragma unroll
        for (int j = 0; j < 8; j++) {
            float* p = x1s + pt * 64 + o0 + j;
            *p = fmaxf(*p, pmax[j]);
        }
    }
    __syncthreads();

    if (tid < 48) {
        int oo  = tid >> 4;
        int pt2 = tid & 15;
        const float* wr = w_out + oo * 64;
        const float* xr = x1s + pt2 * 64;
        float s = 0.f;
#pragma unroll
        for (int o = 0; o < 64; o++) s = fmaf(wr[o], xr[o], s);
        float v = s * (g_out[oo] * rsqrtf(1.f + EPSV)) + b_out[oo];
        out[(b * 3 + oo) * NPTS + p0 + pt2] = lrelu(v);
    }
}

// ---------------------------------------------------------------------------
extern "C" void kernel_launch(void* const* d_in, const int* in_sizes, int n_in,
                              void* d_out, int out_size) {
    const float* x     = (const float*)d_in[0];
    const float* w0    = (const float*)d_in[1];
    const float* g0    = (const float*)d_in[2];
    const float* b0    = (const float*)d_in[3];
    const float* w1    = (const float*)d_in[4];
    const float* g1    = (const float*)d_in[5];
    const float* b1    = (const float*)d_in[6];
    const float* w_out = (const float*)d_in[7];
    const float* g_out = (const float*)d_in[8];
    const float* b_out = (const float*)d_in[9];
    float* out = (float*)d_out;

    const int knn_smem  = NPTS * 16;                                        // 65536
    const int main_smem = (24576 + 20480 + 1920 + 1024 + 384 + 64 + 64) * 4;

    cudaFuncSetAttribute(knn_prep_kernel, cudaFuncAttributeMaxDynamicSharedMemorySize,
                         knn_smem);
    cudaFuncSetAttribute(main_kernel, cudaFuncAttributeMaxDynamicSharedMemorySize,
                         main_smem);

    knn_prep_kernel<<<dim3(NPTS / QPB, BATCH), 256, knn_smem>>>(x, w0, g0, w1, g1);
    main_kernel<<<BATCH * (NPTS / PTS), THR, main_smem>>>(x, b0, b1, w_out,
                                                          g_out, b_out, out);
}

// round 6
// speedup vs baseline: 2.8006x; 1.2461x over previous
#include <cuda_runtime.h>

#define BATCH 4
#define NPTS  4096
#define KNB   20
#define EPSV  1e-5f
#define SLOPE 0.2f

#define PTS 16              // points per block (main kernel)
#define EDG (PTS * KNB)     // 320 edges per block
#define THR 256

#define QPB 8               // queries (= warps) per knn block
#define LL  8               // per-lane list length (register-resident)

// scratch (device globals; no allocations allowed)
__device__ float g_wp[384 * 64];          // reindexed + s1-folded w1: Wp[m*6+c][o]
__device__ float g_w0f[384];              // s0-folded w0
__device__ int   g_idx[BATCH * NPTS * KNB];

__device__ __forceinline__ float lrelu(float v) { return fmaxf(v, SLOPE * v); }

__device__ __forceinline__ float2 ffma2(float2 a, float2 b, float2 c) {
    float2 d;
    asm("fma.rn.f32x2 %0, %1, %2, %3;"
        : "=l"(reinterpret_cast<unsigned long long&>(d))
        : "l"(reinterpret_cast<unsigned long long&>(a)),
          "l"(reinterpret_cast<unsigned long long&>(b)),
          "l"(reinterpret_cast<unsigned long long&>(c)));
    return d;
}
__device__ __forceinline__ float2 fmul2(float2 a, float2 b) {
    float2 d;
    asm("mul.rn.f32x2 %0, %1, %2;"
        : "=l"(reinterpret_cast<unsigned long long&>(d))
        : "l"(reinterpret_cast<unsigned long long&>(a)),
          "l"(reinterpret_cast<unsigned long long&>(b)));
    return d;
}

// monotone float -> uint key (total order, incl. negatives)
__device__ __forceinline__ unsigned fkey(float d) {
    unsigned b = __float_as_uint(d);
    return b ^ ((unsigned)((int)b >> 31) | 0x80000000u);
}

// ---------------------------------------------------------------------------
// KNN: warp per query, register-resident per-lane top-8 + exact warp merge.
// Grid (NPTS/QPB, BATCH) = (512, 4), 256 threads (8 warps), 2 blocks/SM.
// d = ||p||^2 - 2 q.p (constant ||q||^2 shift preserves the reference's
// -||q-p||^2 top_k ordering; self point minimal, included).
// Each lane keeps the 8 smallest over its disjoint 128-candidate subset using
// ONLY statically-indexed (predicated) register arrays. The global top-20 is
// contained in the union of lane top-8s unless some lane owns >=9 of the
// top-20 (detected via packed-key threshold; exact full-rescan fallback).
// Extraction: 20 rounds of warp-min over packed (key,idx) u64 -- exact,
// deterministic, ties -> lowest index (matches top_k). Order of the 20
// indices is irrelevant downstream (max over k).
// ---------------------------------------------------------------------------
__global__ void __launch_bounds__(256, 2) knn_prep_kernel(
    const float* __restrict__ x,
    const float* __restrict__ w0, const float* __restrict__ g0,
    const float* __restrict__ w1, const float* __restrict__ g1)
{
    extern __shared__ float4 pts[];          // 4096 * 16 = 65536 bytes

    const int tid  = threadIdx.x;
    const int lane = tid & 31;
    const int w    = tid >> 5;
    const int b    = blockIdx.y;
    const int q    = blockIdx.x * QPB + w;
    const float* xb = x + b * 3 * NPTS;

    // ---- prep: distributed over the 2048 blocks ----
    {
        const int gt = (blockIdx.y * gridDim.x + blockIdx.x) * 256 + tid;
        const float inv = rsqrtf(1.f + EPSV);
        if (gt < 384) g_w0f[gt] = w0[gt] * g0[gt / 6] * inv;
        if (gt < 384 * 64) {
            int o  = gt & 63;
            int kc = gt >> 6;
            int m  = kc / 6;
            int c  = kc - m * 6;
            g_wp[gt] = g1[o] * inv * w1[(o * 6 + c) * 64 + m];
        }
    }

    // ---- stage batch points (x,y,z,||p||^2) ----
    for (int i = tid; i < NPTS; i += 256) {
        float vx = xb[i], vy = xb[NPTS + i], vz = xb[2 * NPTS + i];
        pts[i] = make_float4(vx, vy, vz, fmaf(vx, vx, fmaf(vy, vy, vz * vz)));
    }
    __syncthreads();

    const float4 qp = pts[q];
    const float qx = qp.x, qy = qp.y, qz = qp.z;

    // ---- per-lane top-8 over 128 strided candidates (registers only) ----
    float nd[LL];
    int   ni[LL];
#pragma unroll
    for (int i = 0; i < LL; i++) { nd[i] = __int_as_float(0x7f800000); ni[i] = 0; }
    float worst = __int_as_float(0x7f800000);
    int   wpos  = 0;

#pragma unroll 4
    for (int t = 0; t < NPTS / 32; t++) {
        const int j = (t << 5) + lane;
        float4 p  = pts[j];
        float dot = fmaf(qx, p.x, fmaf(qy, p.y, qz * p.z));
        float d   = fmaf(-2.f, dot, p.w);
        if (d < worst) {
#pragma unroll
            for (int i = 0; i < LL; i++)
                if (i == wpos) { nd[i] = d; ni[i] = j; }
            worst = nd[0]; wpos = 0;
#pragma unroll
            for (int i = 1; i < LL; i++)
                if (nd[i] > worst) { worst = nd[i]; wpos = i; }
        }
    }

    // ---- pack (key, idx); track lane max for the safety check ----
    unsigned long long v[LL];
    unsigned long long lane_max = 0;
#pragma unroll
    for (int i = 0; i < LL; i++) {
        v[i] = ((unsigned long long)fkey(nd[i]) << 32) | (unsigned)ni[i];
        lane_max = (v[i] > lane_max) ? v[i] : lane_max;
    }

    // ---- exact extraction: 20 rounds of warp-min over the 256 entries ----
    int* obase = g_idx + (b * NPTS + q) * KNB;
    unsigned long long kth = 0;
    for (int r = 0; r < KNB; r++) {
        unsigned long long lmin = v[0]; int lpos = 0;
#pragma unroll
        for (int u = 1; u < LL; u++)
            if (v[u] < lmin) { lmin = v[u]; lpos = u; }
        unsigned long long wmin = lmin;
#pragma unroll
        for (int d = 16; d; d >>= 1) {
            unsigned long long o = __shfl_xor_sync(0xffffffffu, wmin, d);
            wmin = (o < wmin) ? o : wmin;
        }
        if (lmin == wmin) {
#pragma unroll
            for (int u = 0; u < LL; u++)
                if (u == lpos) v[u] = 0xffffffffffffffffull;
        }
        if (lane == 0) obase[r] = (int)(unsigned)(wmin & 0xffffffffull);
        kth = wmin;
    }

    // ---- safety: a miss is possible only if some lane's whole top-8 sits
    //      strictly below the 20th selected key (lane would own >=9 of top-20)
    if (__ballot_sync(0xffffffffu, lane_max < kth)) {
        // exact fallback: 20 rounds of repeated warp-min over ALL candidates
        unsigned long long last = 0;
        for (int r = 0; r < KNB; r++) {
            unsigned long long best = 0xffffffffffffffffull;
            for (int t = 0; t < NPTS / 32; t++) {
                const int j = (t << 5) + lane;
                float4 p  = pts[j];
                float dot = fmaf(qx, p.x, fmaf(qy, p.y, qz * p.z));
                float d   = fmaf(-2.f, dot, p.w);
                unsigned long long kk =
                    ((unsigned long long)fkey(d) << 32) | (unsigned)j;
                if (kk > last && kk < best) best = kk;
            }
#pragma unroll
            for (int d = 16; d; d >>= 1) {
                unsigned long long o = __shfl_xor_sync(0xffffffffu, best, d);
                best = (o < best) ? o : best;
            }
            if (lane == 0) obase[r] = (int)(unsigned)(best & 0xffffffffull);
            last = best;
        }
    }
}

// ---------------------------------------------------------------------------
// Fused main kernel (unchanged, 330us @ fma 70.6%): feat gather -> y1 ->
// packed f32x2 GEMM (E x 384)@(384 x 64) -> BN+LReLU -> max k -> 64->3 conv.
// ---------------------------------------------------------------------------
__global__ void __launch_bounds__(THR, 1) main_kernel(
    const float* __restrict__ x,    const float* __restrict__ b0,
    const float* __restrict__ b1,   const float* __restrict__ w_out,
    const float* __restrict__ g_out, const float* __restrict__ b_out,
    float* __restrict__ out)
{
    extern __shared__ float smem[];
    float* Wp  = smem;                 // 24576  Wp[kc][64]
    float* y1s = smem + 24576;         // 20480  y1s[m][320]
    float* fts = y1s + 20480;          //  1920  fts[c][320]
    float* x1s = fts + 1920;           //  1024  x1s[pt][64]
    float* w0f = x1s + 1024;           //   384
    float* b0s = w0f + 384;            //    64
    float* b1s = b0s + 64;             //    64

    const int tid = threadIdx.x;
    const int b   = blockIdx.x >> 8;
    const int p0  = (blockIdx.x & 255) * PTS;
    const float* xb = x + b * 3 * NPTS;

    for (int e = tid; e < EDG; e += THR) {
        int p  = e / KNB;
        int kk = e - p * KNB;
        int n  = p0 + p;
        int j  = g_idx[(b * NPTS + n) * KNB + kk];
        float xi0 = xb[n],          xi1 = xb[NPTS + n],  xi2 = xb[2 * NPTS + n];
        float xj0 = xb[j],          xj1 = xb[NPTS + j],  xj2 = xb[2 * NPTS + j];
        fts[0 * EDG + e] = xj0 - xi0;
        fts[1 * EDG + e] = xj1 - xi1;
        fts[2 * EDG + e] = xj2 - xi2;
        fts[3 * EDG + e] = xi0;
        fts[4 * EDG + e] = xi1;
        fts[5 * EDG + e] = xi2;
    }

    {
        const float4* src = reinterpret_cast<const float4*>(g_wp);
        float4* dst = reinterpret_cast<float4*>(Wp);
#pragma unroll
        for (int i = 0; i < 24; i++) dst[tid + i * THR] = src[tid + i * THR];
    }
    for (int i = tid; i < 384; i += THR) w0f[i] = g_w0f[i];
    if (tid < 64) { b0s[tid] = b0[tid]; b1s[tid] = b1[tid]; }
    __syncthreads();

    for (int i = tid; i < 64 * EDG; i += THR) {
        int m = i / EDG;
        int e = i - m * EDG;
        const float* wr = w0f + m * 6;
        float v = b0s[m];
        v = fmaf(wr[0], fts[e],           v);
        v = fmaf(wr[1], fts[EDG + e],     v);
        v = fmaf(wr[2], fts[2 * EDG + e], v);
        v = fmaf(wr[3], fts[3 * EDG + e], v);
        v = fmaf(wr[4], fts[4 * EDG + e], v);
        v = fmaf(wr[5], fts[5 * EDG + e], v);
        y1s[i] = lrelu(v);
    }
    __syncthreads();

    const int og = tid & 7;
    const int eg = tid >> 3;
    const int e0 = eg * 10;
    const int o0 = og * 8;

    float2 acc[5][8];
#pragma unroll
    for (int i = 0; i < 5; i++)
#pragma unroll
        for (int j = 0; j < 8; j++) acc[i][j] = make_float2(0.f, 0.f);

#pragma unroll 1
    for (int m = 0; m < 64; m++) {
        float2 yp[5];
        const float* yr = y1s + m * EDG + e0;
#pragma unroll
        for (int i = 0; i < 5; i++)
            yp[i] = *reinterpret_cast<const float2*>(yr + 2 * i);
#pragma unroll
        for (int c = 0; c < 6; c++) {
            const float* wr = Wp + (m * 6 + c) * 64 + o0;
            float4 wa = *reinterpret_cast<const float4*>(wr);
            float4 wb = *reinterpret_cast<const float4*>(wr + 4);
            float2 wd[8];
            wd[0] = make_float2(wa.x, wa.x); wd[1] = make_float2(wa.y, wa.y);
            wd[2] = make_float2(wa.z, wa.z); wd[3] = make_float2(wa.w, wa.w);
            wd[4] = make_float2(wb.x, wb.x); wd[5] = make_float2(wb.y, wb.y);
            wd[6] = make_float2(wb.z, wb.z); wd[7] = make_float2(wb.w, wb.w);
            const float* fr = fts + c * EDG + e0;
#pragma unroll
            for (int i = 0; i < 5; i++) {
                float2 fp = *reinterpret_cast<const float2*>(fr + 2 * i);
                float2 a  = fmul2(yp[i], fp);
#pragma unroll
                for (int j = 0; j < 8; j++)
                    acc[i][j] = ffma2(a, wd[j], acc[i][j]);
            }
        }
    }

    float pmax[8];
#pragma unroll
    for (int j = 0; j < 8; j++) pmax[j] = -3.4e38f;
#pragma unroll
    for (int j = 0; j < 8; j++) {
        float bb = b1s[o0 + j];
#pragma unroll
        for (int i = 0; i < 5; i++) {
            float vx = lrelu(acc[i][j].x + bb);
            float vy = lrelu(acc[i][j].y + bb);
            pmax[j] = fmaxf(pmax[j], fmaxf(vx, vy));
        }
    }
    const int pt = eg >> 1;
    if ((eg & 1) == 0) {
#pragma unroll
        for (int j = 0; j < 8; j++) x1s[pt * 64 + o0 + j] = pmax[j];
    }
    __syncthreads();
    if (eg & 1) {
#pragma unroll
        for (int j = 0; j < 8; j++) {
            float* p = x1s + pt * 64 + o0 + j;
            *p = fmaxf(*p, pmax[j]);
        }
    }
    __syncthreads();

    if (tid < 48) {
        int oo  = tid >> 4;
        int pt2 = tid & 15;
        const float* wr = w_out + oo * 64;
        const float* xr = x1s + pt2 * 64;
        float s = 0.f;
#pragma unroll
        for (int o = 0; o < 64; o++) s = fmaf(wr[o], xr[o], s);
        float v = s * (g_out[oo] * rsqrtf(1.f + EPSV)) + b_out[oo];
        out[(b * 3 + oo) * NPTS + p0 + pt2] = lrelu(v);
    }
}

// ---------------------------------------------------------------------------
extern "C" void kernel_launch(void* const* d_in, const int* in_sizes, int n_in,
                              void* d_out, int out_size) {
    const float* x     = (const float*)d_in[0];
    const float* w0    = (const float*)d_in[1];
    const float* g0    = (const float*)d_in[2];
    const float* b0    = (const float*)d_in[3];
    const float* w1    = (const float*)d_in[4];
    const float* g1    = (const float*)d_in[5];
    const float* b1    = (const float*)d_in[6];
    const float* w_out = (const float*)d_in[7];
    const float* g_out = (const float*)d_in[8];
    const float* b_out = (const float*)d_in[9];
    float* out = (float*)d_out;

    const int knn_smem  = NPTS * 16;                                        // 65536
    const int main_smem = (24576 + 20480 + 1920 + 1024 + 384 + 64 + 64) * 4;

    cudaFuncSetAttribute(knn_prep_kernel, cudaFuncAttributeMaxDynamicSharedMemorySize,
                         knn_smem);
    cudaFuncSetAttribute(main_kernel, cudaFuncAttributeMaxDynamicSharedMemorySize,
                         main_smem);

    knn_prep_kernel<<<dim3(NPTS / QPB, BATCH), 256, knn_smem>>>(x, w0, g0, w1, g1);
    main_kernel<<<BATCH * (NPTS / PTS), THR, main_smem>>>(x, b0, b1, w_out,
                                                          g_out, b_out, out);
}

// round 7
// speedup vs baseline: 3.6822x; 1.3148x over previous
#include <cuda_runtime.h>

#define BATCH 4
#define NPTS  4096
#define KNB   20
#define EPSV  1e-5f
#define SLOPE 0.2f

#define PTS 16              // points per block (main kernel)
#define EDG (PTS * KNB)     // 320 edges per block
#define THR 256

#define QPB 8               // queries (= warps) per knn block
#define BCAP 128            // per-warp pass-2 buffer capacity

// scratch (device globals; no allocations allowed)
__device__ float g_wp[384 * 64];          // reindexed + s1-folded w1: Wp[m*6+c][o]
__device__ float g_w0f[384];              // s0-folded w0
__device__ int   g_idx[BATCH * NPTS * KNB];

__device__ __forceinline__ float lrelu(float v) { return fmaxf(v, SLOPE * v); }

__device__ __forceinline__ float2 ffma2(float2 a, float2 b, float2 c) {
    float2 d;
    asm("fma.rn.f32x2 %0, %1, %2, %3;"
        : "=l"(reinterpret_cast<unsigned long long&>(d))
        : "l"(reinterpret_cast<unsigned long long&>(a)),
          "l"(reinterpret_cast<unsigned long long&>(b)),
          "l"(reinterpret_cast<unsigned long long&>(c)));
    return d;
}
__device__ __forceinline__ float2 fmul2(float2 a, float2 b) {
    float2 d;
    asm("mul.rn.f32x2 %0, %1, %2;"
        : "=l"(reinterpret_cast<unsigned long long&>(d))
        : "l"(reinterpret_cast<unsigned long long&>(a)),
          "l"(reinterpret_cast<unsigned long long&>(b)));
    return d;
}

// monotone float -> uint key (total order, incl. negatives)
__device__ __forceinline__ unsigned fkey(float d) {
    unsigned b = __float_as_uint(d);
    return b ^ ((unsigned)((int)b >> 31) | 0x80000000u);
}

// ---------------------------------------------------------------------------
// KNN: warp per query, exact threshold-filter select + fused weight prep.
// Grid (NPTS/QPB, BATCH) = (512, 4), 256 threads (8 warps), 2 blocks/SM.
// d = ||p||^2 - 2 q.p (constant ||q||^2 shift preserves reference's
// -||q-p||^2 top_k ordering; self point minimal, included).
// Phase 1 (branchless): per-lane running min over its disjoint 128-candidate
//   strided subset. Phase T: T = 20th smallest of the 32 lane mins (with
//   multiplicity). The 20 smallest lane-mins are >=20 distinct elements with
//   d <= T, so the global 20th smallest <= T and every top-20 element passes
//   the filter d <= T. Phase 2: ballot-compact all passers (packed key,idx)
//   into a small smem buffer (expected ~30). Phase 3: exact top-20 by 20
//   warp-min rounds (ties -> lowest index, matching top_k). Output order is
//   irrelevant downstream (max over k). nb > BCAP -> exact full fallback.
// ---------------------------------------------------------------------------
__global__ void __launch_bounds__(256, 2) knn_prep_kernel(
    const float* __restrict__ x,
    const float* __restrict__ w0, const float* __restrict__ g0,
    const float* __restrict__ w1, const float* __restrict__ g1)
{
    extern __shared__ char dsm[];
    float4*             pts = reinterpret_cast<float4*>(dsm);                 // 65536
    unsigned long long* buf = reinterpret_cast<unsigned long long*>(dsm + 65536); // 8192

    const int tid  = threadIdx.x;
    const int lane = tid & 31;
    const int w    = tid >> 5;
    const int b    = blockIdx.y;
    const int q    = blockIdx.x * QPB + w;
    const float* xb = x + b * 3 * NPTS;

    // ---- prep: distributed over the 2048 blocks ----
    {
        const int gt = (blockIdx.y * gridDim.x + blockIdx.x) * 256 + tid;
        const float inv = rsqrtf(1.f + EPSV);
        if (gt < 384) g_w0f[gt] = w0[gt] * g0[gt / 6] * inv;
        if (gt < 384 * 64) {
            int o  = gt & 63;
            int kc = gt >> 6;
            int m  = kc / 6;
            int c  = kc - m * 6;
            g_wp[gt] = g1[o] * inv * w1[(o * 6 + c) * 64 + m];
        }
    }

    // ---- stage batch points (x,y,z,||p||^2) ----
    for (int i = tid; i < NPTS; i += 256) {
        float vx = xb[i], vy = xb[NPTS + i], vz = xb[2 * NPTS + i];
        pts[i] = make_float4(vx, vy, vz, fmaf(vx, vx, fmaf(vy, vy, vz * vz)));
    }
    __syncthreads();

    const float4 qp = pts[q];
    const float qx = qp.x, qy = qp.y, qz = qp.z;
    const float INF = __int_as_float(0x7f800000);

    // ---- phase 1: branchless per-lane min (4 independent chains) ----
    float m0 = INF, m1 = INF, m2 = INF, m3 = INF;
#pragma unroll 2
    for (int t = 0; t < NPTS / 32; t += 4) {
        float4 p0 = pts[((t + 0) << 5) + lane];
        float4 p1 = pts[((t + 1) << 5) + lane];
        float4 p2 = pts[((t + 2) << 5) + lane];
        float4 p3 = pts[((t + 3) << 5) + lane];
        m0 = fminf(m0, fmaf(-2.f, fmaf(qx, p0.x, fmaf(qy, p0.y, qz * p0.z)), p0.w));
        m1 = fminf(m1, fmaf(-2.f, fmaf(qx, p1.x, fmaf(qy, p1.y, qz * p1.z)), p1.w));
        m2 = fminf(m2, fmaf(-2.f, fmaf(qx, p2.x, fmaf(qy, p2.y, qz * p2.z)), p2.w));
        m3 = fminf(m3, fmaf(-2.f, fmaf(qx, p3.x, fmaf(qy, p3.y, qz * p3.z)), p3.w));
    }
    float val = fminf(fminf(m0, m1), fminf(m2, m3));

    // ---- threshold: T = 20th smallest lane-min (with multiplicity) ----
    float T = INF;
    for (int r = 0; r < KNB; r++) {
        float wmin = val;
#pragma unroll
        for (int d = 16; d; d >>= 1)
            wmin = fminf(wmin, __shfl_xor_sync(0xffffffffu, wmin, d));
        unsigned msk = __ballot_sync(0xffffffffu, val == wmin);
        if (lane == (__ffs(msk) - 1)) val = INF;
        T = wmin;
    }

    // ---- phase 2: compact all candidates with d <= T (same FMA expr) ----
    unsigned long long* myb = buf + w * BCAP;
    unsigned nb = 0;
    for (int t = 0; t < NPTS / 32; t++) {
        const int j = (t << 5) + lane;
        float4 p  = pts[j];
        float d   = fmaf(-2.f, fmaf(qx, p.x, fmaf(qy, p.y, qz * p.z)), p.w);
        bool pass = (d <= T);
        unsigned mask = __ballot_sync(0xffffffffu, pass);
        if (mask) {
            if (pass) {
                unsigned pos = nb + __popc(mask & ((1u << lane) - 1u));
                if (pos < BCAP)
                    myb[pos] = ((unsigned long long)fkey(d) << 32) | (unsigned)j;
            }
            nb += __popc(mask);
        }
    }
    __syncwarp();

    // ---- phase 3: exact top-20 from buffer (nb >= 20 guaranteed) ----
    int* obase = g_idx + (b * NPTS + q) * KNB;
    if (nb <= BCAP) {
        unsigned long long v[BCAP / 32];
#pragma unroll
        for (int u = 0; u < BCAP / 32; u++) {
            int t = lane + u * 32;
            v[u] = (t < (int)nb) ? myb[t] : 0xffffffffffffffffull;
        }
        for (int r = 0; r < KNB; r++) {
            unsigned long long lmin = v[0]; int lpos = 0;
#pragma unroll
            for (int u = 1; u < BCAP / 32; u++)
                if (v[u] < lmin) { lmin = v[u]; lpos = u; }
            unsigned long long wmin = lmin;
#pragma unroll
            for (int d = 16; d; d >>= 1) {
                unsigned long long o = __shfl_xor_sync(0xffffffffu, wmin, d);
                wmin = (o < wmin) ? o : wmin;
            }
            if (lmin == wmin) {
#pragma unroll
                for (int u = 0; u < BCAP / 32; u++)
                    if (u == lpos) v[u] = 0xffffffffffffffffull;
            }
            if (lane == 0) obase[r] = (int)(unsigned)(wmin & 0xffffffffull);
        }
    } else {
        // pathological fallback: exact repeated warp-min over all candidates
        unsigned long long last = 0;
        for (int r = 0; r < KNB; r++) {
            unsigned long long best = 0xffffffffffffffffull;
            for (int t = 0; t < NPTS / 32; t++) {
                const int j = (t << 5) + lane;
                float4 p  = pts[j];
                float d   = fmaf(-2.f, fmaf(qx, p.x, fmaf(qy, p.y, qz * p.z)), p.w);
                unsigned long long kk =
                    ((unsigned long long)fkey(d) << 32) | (unsigned)j;
                if (kk > last && kk < best) best = kk;
            }
#pragma unroll
            for (int d = 16; d; d >>= 1) {
                unsigned long long o = __shfl_xor_sync(0xffffffffu, best, d);
                best = (o < best) ? o : best;
            }
            if (lane == 0) obase[r] = (int)(unsigned)(best & 0xffffffffull);
            last = best;
        }
    }
}

// ---------------------------------------------------------------------------
// Fused main kernel (unchanged, 330us @ fma 70.8%): feat gather -> y1 ->
// packed f32x2 GEMM (E x 384)@(384 x 64) -> BN+LReLU -> max k -> 64->3 conv.
// ---------------------------------------------------------------------------
__global__ void __launch_bounds__(THR, 1) main_kernel(
    const float* __restrict__ x,    const float* __restrict__ b0,
    const float* __restrict__ b1,   const float* __restrict__ w_out,
    const float* __restrict__ g_out, const float* __restrict__ b_out,
    float* __restrict__ out)
{
    extern __shared__ float smem[];
    float* Wp  = smem;                 // 24576  Wp[kc][64]
    float* y1s = smem + 24576;         // 20480  y1s[m][320]
    float* fts = y1s + 20480;          //  1920  fts[c][320]
    float* x1s = fts + 1920;           //  1024  x1s[pt][64]
    float* w0f = x1s + 1024;           //   384
    float* b0s = w0f + 384;            //    64
    float* b1s = b0s + 64;             //    64

    const int tid = threadIdx.x;
    const int b   = blockIdx.x >> 8;
    const int p0  = (blockIdx.x & 255) * PTS;
    const float* xb = x + b * 3 * NPTS;

    for (int e = tid; e < EDG; e += THR) {
        int p  = e / KNB;
        int kk = e - p * KNB;
        int n  = p0 + p;
        int j  = g_idx[(b * NPTS + n) * KNB + kk];
        float xi0 = xb[n],          xi1 = xb[NPTS + n],  xi2 = xb[2 * NPTS + n];
        float xj0 = xb[j],          xj1 = xb[NPTS + j],  xj2 = xb[2 * NPTS + j];
        fts[0 * EDG + e] = xj0 - xi0;
        fts[1 * EDG + e] = xj1 - xi1;
        fts[2 * EDG + e] = xj2 - xi2;
        fts[3 * EDG + e] = xi0;
        fts[4 * EDG + e] = xi1;
        fts[5 * EDG + e] = xi2;
    }

    {
        const float4* src = reinterpret_cast<const float4*>(g_wp);
        float4* dst = reinterpret_cast<float4*>(Wp);
#pragma unroll
        for (int i = 0; i < 24; i++) dst[tid + i * THR] = src[tid + i * THR];
    }
    for (int i = tid; i < 384; i += THR) w0f[i] = g_w0f[i];
    if (tid < 64) { b0s[tid] = b0[tid]; b1s[tid] = b1[tid]; }
    __syncthreads();

    for (int i = tid; i < 64 * EDG; i += THR) {
        int m = i / EDG;
        int e = i - m * EDG;
        const float* wr = w0f + m * 6;
        float v = b0s[m];
        v = fmaf(wr[0], fts[e],           v);
        v = fmaf(wr[1], fts[EDG + e],     v);
        v = fmaf(wr[2], fts[2 * EDG + e], v);
        v = fmaf(wr[3], fts[3 * EDG + e], v);
        v = fmaf(wr[4], fts[4 * EDG + e], v);
        v = fmaf(wr[5], fts[5 * EDG + e], v);
        y1s[i] = lrelu(v);
    }
    __syncthreads();

    const int og = tid & 7;
    const int eg = tid >> 3;
    const int e0 = eg * 10;
    const int o0 = og * 8;

    float2 acc[5][8];
#pragma unroll
    for (int i = 0; i < 5; i++)
#pragma unroll
        for (int j = 0; j < 8; j++) acc[i][j] = make_float2(0.f, 0.f);

#pragma unroll 1
    for (int m = 0; m < 64; m++) {
        float2 yp[5];
        const float* yr = y1s + m * EDG + e0;
#pragma unroll
        for (int i = 0; i < 5; i++)
            yp[i] = *reinterpret_cast<const float2*>(yr + 2 * i);
#pragma unroll
        for (int c = 0; c < 6; c++) {
            const float* wr = Wp + (m * 6 + c) * 64 + o0;
            float4 wa = *reinterpret_cast<const float4*>(wr);
            float4 wb = *reinterpret_cast<const float4*>(wr + 4);
            float2 wd[8];
            wd[0] = make_float2(wa.x, wa.x); wd[1] = make_float2(wa.y, wa.y);
            wd[2] = make_float2(wa.z, wa.z); wd[3] = make_float2(wa.w, wa.w);
            wd[4] = make_float2(wb.x, wb.x); wd[5] = make_float2(wb.y, wb.y);
            wd[6] = make_float2(wb.z, wb.z); wd[7] = make_float2(wb.w, wb.w);
            const float* fr = fts + c * EDG + e0;
#pragma unroll
            for (int i = 0; i < 5; i++) {
                float2 fp = *reinterpret_cast<const float2*>(fr + 2 * i);
                float2 a  = fmul2(yp[i], fp);
#pragma unroll
                for (int j = 0; j < 8; j++)
                    acc[i][j] = ffma2(a, wd[j], acc[i][j]);
            }
        }
    }

    float pmax[8];
#pragma unroll
    for (int j = 0; j < 8; j++) pmax[j] = -3.4e38f;
#pragma unroll
    for (int j = 0; j < 8; j++) {
        float bb = b1s[o0 + j];
#pragma unroll
        for (int i = 0; i < 5; i++) {
            float vx = lrelu(acc[i][j].x + bb);
            float vy = lrelu(acc[i][j].y + bb);
            pmax[j] = fmaxf(pmax[j], fmaxf(vx, vy));
        }
    }
    const int pt = eg >> 1;
    if ((eg & 1) == 0) {
#pragma unroll
        for (int j = 0; j < 8; j++) x1s[pt * 64 + o0 + j] = pmax[j];
    }
    __syncthreads();
    if (eg & 1) {
#pragma unroll
        for (int j = 0; j < 8; j++) {
            float* p = x1s + pt * 64 + o0 + j;
            *p = fmaxf(*p, pmax[j]);
        }
    }
    __syncthreads();

    if (tid < 48) {
        int oo  = tid >> 4;
        int pt2 = tid & 15;
        const float* wr = w_out + oo * 64;
        const float* xr = x1s + pt2 * 64;
        float s = 0.f;
#pragma unroll
        for (int o = 0; o < 64; o++) s = fmaf(wr[o], xr[o], s);
        float v = s * (g_out[oo] * rsqrtf(1.f + EPSV)) + b_out[oo];
        out[(b * 3 + oo) * NPTS + p0 + pt2] = lrelu(v);
    }
}

// ---------------------------------------------------------------------------
extern "C" void kernel_launch(void* const* d_in, const int* in_sizes, int n_in,
                              void* d_out, int out_size) {
    const float* x     = (const float*)d_in[0];
    const float* w0    = (const float*)d_in[1];
    const float* g0    = (const float*)d_in[2];
    const float* b0    = (const float*)d_in[3];
    const float* w1    = (const float*)d_in[4];
    const float* g1    = (const float*)d_in[5];
    const float* b1    = (const float*)d_in[6];
    const float* w_out = (const float*)d_in[7];
    const float* g_out = (const float*)d_in[8];
    const float* b_out = (const float*)d_in[9];
    float* out = (float*)d_out;

    const int knn_smem  = NPTS * 16 + QPB * BCAP * 8;                       // 73728
    const int main_smem = (24576 + 20480 + 1920 + 1024 + 384 + 64 + 64) * 4;

    cudaFuncSetAttribute(knn_prep_kernel, cudaFuncAttributeMaxDynamicSharedMemorySize,
                         knn_smem);
    cudaFuncSetAttribute(main_kernel, cudaFuncAttributeMaxDynamicSharedMemorySize,
                         main_smem);

    knn_prep_kernel<<<dim3(NPTS / QPB, BATCH), 256, knn_smem>>>(x, w0, g0, w1, g1);
    main_kernel<<<BATCH * (NPTS / PTS), THR, main_smem>>>(x, b0, b1, w_out,
                                                          g_out, b_out, out);
}